// round 1
// baseline (speedup 1.0000x reference)
#include <cuda_runtime.h>
#include <cstdint>

// TemporalEncoder: fc_in(64->128) + GRU(128->8) over (B=512, S=2048).
// Strategy:
//  prep:  W_comb = W_ih @ W_in (24x64), biases folded, rows pre-scaled by
//         c1=-log2(e) (r,z gates, sigmoid via exp2) / c2=2*log2(e) (n gate, tanh via exp2).
//  proj:  gates[b,s,24] = W_comb @ a  (f32x2 packed FMA), written to a device-global buffer.
//  scan:  512 chains x 2048 sequential GRU steps; 8 lanes per chain, h broadcast
//         via shfl.idx; gate loads software-pipelined 8 steps ahead.

#define BATCH 512
#define SEQ   2048
#define INSZ  64
#define HID   128
#define NITEMS (BATCH * SEQ)

#define C1f (-1.4426950408889634f)   // -log2(e)
#define C2f ( 2.8853900817779268f)   // 2*log2(e)

typedef unsigned long long ull;

__device__ float g_Wc[24 * 64];      // scaled combined weights
__device__ float g_bc[24];           // scaled combined biases (bhh folded for r,z)
__device__ float g_Whh_s[24 * 8];    // scaled hidden->hidden weights
__device__ float g_bhn_s[8];         // scaled bhn (n-gate hidden bias)
__device__ float g_gbuf[(size_t)NITEMS * 24];  // 96 MB gate buffer

__device__ __forceinline__ ull pack2(float lo, float hi) {
    ull r; asm("mov.b64 %0, {%1,%2};" : "=l"(r) : "f"(lo), "f"(hi)); return r;
}
__device__ __forceinline__ ull fma2(ull a, ull b, ull c) {
    ull d; asm("fma.rn.f32x2 %0, %1, %2, %3;" : "=l"(d) : "l"(a), "l"(b), "l"(c)); return d;
}
__device__ __forceinline__ float2 unpack2(ull v) {
    float lo, hi; asm("mov.b64 {%0,%1}, %2;" : "=f"(lo), "=f"(hi) : "l"(v));
    return make_float2(lo, hi);
}

// ---------------- prep: fuse the two linears, fold biases + scales ----------------
__global__ void prep_kernel(const float* __restrict__ Win,  // [128,64]
                            const float* __restrict__ bin,  // [128]
                            const float* __restrict__ Wih,  // [24,128]
                            const float* __restrict__ Whh,  // [24,8]
                            const float* __restrict__ bih,  // [24]
                            const float* __restrict__ bhh)  // [24]
{
    int t = threadIdx.x;  // 256 threads, 1 block
    for (int e = t; e < 24 * 64; e += 256) {
        int g = e >> 6, i = e & 63;
        float s = 0.f;
        for (int h = 0; h < HID; h++) s += Wih[g * HID + h] * Win[h * INSZ + i];
        g_Wc[e] = ((g < 16) ? C1f : C2f) * s;
    }
    if (t < 24) {
        int g = t;
        float s = 0.f;
        for (int h = 0; h < HID; h++) s += Wih[g * HID + h] * bin[h];
        s += bih[g];
        if (g < 16) { s += bhh[g]; g_bc[g] = C1f * s; }  // fold bhr/bhz
        else        {              g_bc[g] = C2f * s; }  // bhn stays separate
    }
    if (t < 24 * 8) {
        int g = t >> 3;
        g_Whh_s[t] = ((g < 16) ? C1f : C2f) * Whh[t];
    }
    if (t < 8) g_bhn_s[t] = C2f * bhh[16 + t];
}

// ---------------- proj: gates = W_comb @ a, packed f32x2 FMA ----------------
__global__ void __launch_bounds__(256) proj_kernel(const float* __restrict__ A) {
    __shared__ __align__(16) float sW[24 * 64];
    __shared__ float sb[24];
    for (int i = threadIdx.x; i < 24 * 64; i += 256) sW[i] = g_Wc[i];
    if (threadIdx.x < 24) sb[threadIdx.x] = g_bc[threadIdx.x];
    __syncthreads();

    int item = blockIdx.x * 256 + threadIdx.x;
    const float4* ap = reinterpret_cast<const float4*>(A + (size_t)item * INSZ);

    ull a2[32];
#pragma unroll
    for (int c = 0; c < 16; c++) {
        float4 v = ap[c];
        a2[2 * c]     = pack2(v.x, v.y);
        a2[2 * c + 1] = pack2(v.z, v.w);
    }

    float res[24];
#pragma unroll
    for (int g = 0; g < 24; g++) {
        const ulonglong2* wp = reinterpret_cast<const ulonglong2*>(sW + g * 64);
        ull acc0 = pack2(sb[g], 0.f);
        ull acc1 = pack2(0.f, 0.f);
#pragma unroll
        for (int p = 0; p < 16; p++) {
            ulonglong2 w = wp[p];
            acc0 = fma2(w.x, a2[2 * p], acc0);
            acc1 = fma2(w.y, a2[2 * p + 1], acc1);
        }
        float2 s0 = unpack2(acc0), s1 = unpack2(acc1);
        res[g] = (s0.x + s0.y) + (s1.x + s1.y);
    }

    float* op = g_gbuf + (size_t)item * 24;
#pragma unroll
    for (int q = 0; q < 6; q++) {
        reinterpret_cast<float4*>(op)[q] =
            make_float4(res[4 * q], res[4 * q + 1], res[4 * q + 2], res[4 * q + 3]);
    }
}

// ---------------- scan: sequential GRU, 8 lanes per chain ----------------
__global__ void __launch_bounds__(64) scan_kernel(float* __restrict__ out) {
    int lane  = threadIdx.x & 31;
    int j     = threadIdx.x & 7;       // hidden unit owned by this lane
    int gb    = lane & ~7;             // base lane of this chain's 8-lane group
    int chain = blockIdx.x * 8 + (threadIdx.x >> 3);

    float wr[8], wz[8], wn[8];
#pragma unroll
    for (int k = 0; k < 8; k++) {
        wr[k] = g_Whh_s[j * 8 + k];
        wz[k] = g_Whh_s[(8 + j) * 8 + k];
        wn[k] = g_Whh_s[(16 + j) * 8 + k];
    }
    float bq = g_bhn_s[j];

    const float* gp = g_gbuf + (size_t)chain * SEQ * 24;

    // software pipeline: 8 steps of gate values in registers
    float br[8], bz[8], bn[8];
#pragma unroll
    for (int d = 0; d < 8; d++) {
        br[d] = gp[d * 24 + j];
        bz[d] = gp[d * 24 + 8 + j];
        bn[d] = gp[d * 24 + 16 + j];
    }

    float h = 0.f;
    for (int t = 0; t < SEQ; t += 8) {
#pragma unroll
        for (int d = 0; d < 8; d++) {
            // broadcast full h vector across the 8-lane group (independent shfl.idx)
            float hv[8];
#pragma unroll
            for (int k = 0; k < 8; k++) hv[k] = __shfl_sync(0xffffffffu, h, gb + k);

            float dr = br[d], dz = bz[d], q = bq;
            float gn = bn[d];
#pragma unroll
            for (int k = 0; k < 8; k++) {
                dr = fmaf(wr[k], hv[k], dr);
                dz = fmaf(wz[k], hv[k], dz);
                q  = fmaf(wn[k], hv[k], q);
            }

            // prefetch step t+8+d (off the critical path)
            int s2 = t + 8 + d; if (s2 > SEQ - 1) s2 = SEQ - 1;
            const float* np = gp + (size_t)s2 * 24;
            br[d] = np[j]; bz[d] = np[8 + j]; bn[d] = np[16 + j];

            // r = sigmoid(pre_r): dr is already -log2e*pre_r
            float er = exp2f(dr);
            float r  = __fdividef(1.f, 1.f + er);
            float ez = exp2f(dz);
            float z  = __fdividef(1.f, 1.f + ez);
            // n = tanh(v), with 2*log2e*v = gn + r*q
            float na = fmaf(r, q, gn);
            float en = exp2f(na);
            float n  = 1.f - __fdividef(2.f, en + 1.f);
            // h' = (1-z)*n + z*h
            h = fmaf(z, h - n, n);
        }
    }
    out[chain * 8 + j] = h;
}

extern "C" void kernel_launch(void* const* d_in, const int* in_sizes, int n_in,
                              void* d_out, int out_size) {
    const float* A   = (const float*)d_in[0];
    const float* Win = (const float*)d_in[1];
    const float* bin = (const float*)d_in[2];
    const float* Wih = (const float*)d_in[3];
    const float* Whh = (const float*)d_in[4];
    const float* bih = (const float*)d_in[5];
    const float* bhh = (const float*)d_in[6];

    prep_kernel<<<1, 256>>>(Win, bin, Wih, Whh, bih, bhh);
    proj_kernel<<<NITEMS / 256, 256>>>(A);
    scan_kernel<<<BATCH / 8, 64>>>((float*)d_out);
}

// round 2
// speedup vs baseline: 1.1385x; 1.1385x over previous
#include <cuda_runtime.h>
#include <cstdint>

// TemporalEncoder: fc_in(64->128) + GRU(128->8) over (B=512, S=2048).
//  prep:  W_comb = W_ih @ W_in (24x64), biases folded, rows pre-scaled by
//         c1=-log2(e) (r,z: sigmoid via exp2) / c2=2*log2(e) (n: tanh via exp2).
//  proj:  gates[b,s,24] = W_comb @ a  (f32x2 packed FMA) -> device-global buffer.
//  scan:  512 chains x 2048 GRU steps; 8 lanes/chain, h via shfl.idx,
//         single-MUFU ex2/rcp approx, gate loads pipelined 8 steps ahead.

#define BATCH 512
#define SEQ   2048
#define INSZ  64
#define HID   128
#define NITEMS (BATCH * SEQ)

#define C1f (-1.4426950408889634f)   // -log2(e)
#define C2f ( 2.8853900817779268f)   // 2*log2(e)

typedef unsigned long long ull;

__device__ float g_Wc[24 * 64];
__device__ float g_bc[24];
__device__ float g_Whh_s[24 * 8];
__device__ float g_bhn_s[8];
__device__ float g_gbuf[(size_t)NITEMS * 24];  // 96 MB gate buffer

__device__ __forceinline__ ull pack2(float lo, float hi) {
    ull r; asm("mov.b64 %0, {%1,%2};" : "=l"(r) : "f"(lo), "f"(hi)); return r;
}
__device__ __forceinline__ ull fma2(ull a, ull b, ull c) {
    ull d; asm("fma.rn.f32x2 %0, %1, %2, %3;" : "=l"(d) : "l"(a), "l"(b), "l"(c)); return d;
}
__device__ __forceinline__ float2 unpack2(ull v) {
    float lo, hi; asm("mov.b64 {%0,%1}, %2;" : "=f"(lo), "=f"(hi) : "l"(v));
    return make_float2(lo, hi);
}
__device__ __forceinline__ float ex2a(float x) {
    float y; asm("ex2.approx.ftz.f32 %0, %1;" : "=f"(y) : "f"(x)); return y;
}
__device__ __forceinline__ float rcpa(float x) {
    float y; asm("rcp.approx.ftz.f32 %0, %1;" : "=f"(y) : "f"(x)); return y;
}

// ---------------- prep: fuse linears, fold biases + scales (smem-staged) ----------------
__global__ void __launch_bounds__(256) prep_kernel(
    const float* __restrict__ Win,  // [128,64]
    const float* __restrict__ bin,  // [128]
    const float* __restrict__ Wih,  // [24,128]
    const float* __restrict__ Whh,  // [24,8]
    const float* __restrict__ bih,  // [24]
    const float* __restrict__ bhh)  // [24]
{
    __shared__ float sWin[HID * INSZ];   // 32 KB
    __shared__ float sWih[24 * HID];     // 12 KB
    __shared__ float sbin[HID];
    int t = threadIdx.x;
    for (int i = t; i < HID * INSZ; i += 256) sWin[i] = Win[i];
    for (int i = t; i < 24 * HID; i += 256) sWih[i] = Wih[i];
    if (t < HID) sbin[t] = bin[t];
    __syncthreads();

#pragma unroll
    for (int rep = 0; rep < 6; rep++) {
        int e = t + rep * 256;            // 0..1535
        int g = e >> 6, i = e & 63;
        float s0 = 0.f, s1 = 0.f;
        for (int h = 0; h < HID; h += 2) {
            s0 = fmaf(sWih[g * HID + h],     sWin[h * INSZ + i],       s0);
            s1 = fmaf(sWih[g * HID + h + 1], sWin[(h + 1) * INSZ + i], s1);
        }
        g_Wc[e] = ((g < 16) ? C1f : C2f) * (s0 + s1);
    }
    if (t < 24) {
        int g = t;
        float s = 0.f;
        for (int h = 0; h < HID; h++) s = fmaf(sWih[g * HID + h], sbin[h], s);
        s += bih[g];
        if (g < 16) { s += bhh[g]; g_bc[g] = C1f * s; }
        else        {              g_bc[g] = C2f * s; }
    }
    if (t < 24 * 8) {
        int g = t >> 3;
        g_Whh_s[t] = ((g < 16) ? C1f : C2f) * Whh[t];
    }
    if (t < 8) g_bhn_s[t] = C2f * bhh[16 + t];
}

// ---------------- proj: gates = W_comb @ a ----------------
__global__ void __launch_bounds__(256) proj_kernel(const float* __restrict__ A) {
    __shared__ __align__(16) float sW[24 * 64];
    __shared__ float sb[24];
    for (int i = threadIdx.x; i < 24 * 64; i += 256) sW[i] = g_Wc[i];
    if (threadIdx.x < 24) sb[threadIdx.x] = g_bc[threadIdx.x];
    __syncthreads();

    int item = blockIdx.x * 256 + threadIdx.x;
    const float4* ap = reinterpret_cast<const float4*>(A + (size_t)item * INSZ);

    ull a2[32];
#pragma unroll
    for (int c = 0; c < 16; c++) {
        float4 v = ap[c];
        a2[2 * c]     = pack2(v.x, v.y);
        a2[2 * c + 1] = pack2(v.z, v.w);
    }

    float res[24];
#pragma unroll
    for (int g = 0; g < 24; g++) {
        const ulonglong2* wp = reinterpret_cast<const ulonglong2*>(sW + g * 64);
        ull acc0 = pack2(sb[g], 0.f);
        ull acc1 = pack2(0.f, 0.f);
#pragma unroll
        for (int p = 0; p < 16; p++) {
            ulonglong2 w = wp[p];
            acc0 = fma2(w.x, a2[2 * p], acc0);
            acc1 = fma2(w.y, a2[2 * p + 1], acc1);
        }
        float2 s0 = unpack2(acc0), s1 = unpack2(acc1);
        res[g] = (s0.x + s0.y) + (s1.x + s1.y);
    }

    float* op = g_gbuf + (size_t)item * 24;
#pragma unroll
    for (int q = 0; q < 6; q++) {
        reinterpret_cast<float4*>(op)[q] =
            make_float4(res[4 * q], res[4 * q + 1], res[4 * q + 2], res[4 * q + 3]);
    }
}

// ---------------- scan: sequential GRU, 8 lanes per chain ----------------
__global__ void __launch_bounds__(32) scan_kernel(float* __restrict__ out) {
    int lane  = threadIdx.x;           // 0..31
    int j     = lane & 7;              // hidden unit of this lane
    int gb    = lane & ~7;             // base lane of the 8-lane group
    int chain = blockIdx.x * 4 + (lane >> 3);

    float wr[8], wz[8], wn[8];
#pragma unroll
    for (int k = 0; k < 8; k++) {
        wr[k] = g_Whh_s[j * 8 + k];
        wz[k] = g_Whh_s[(8 + j) * 8 + k];
        wn[k] = g_Whh_s[(16 + j) * 8 + k];
    }
    float bq = g_bhn_s[j];

    const float* gp = g_gbuf + (size_t)chain * SEQ * 24;

    // software pipeline: 8 steps of gates in registers
    float br[8], bz[8], bn[8];
#pragma unroll
    for (int d = 0; d < 8; d++) {
        br[d] = gp[d * 24 + j];
        bz[d] = gp[d * 24 + 8 + j];
        bn[d] = gp[d * 24 + 16 + j];
    }

    float h = 0.f;
    for (int t = 0; t < SEQ; t += 8) {
#pragma unroll
        for (int d = 0; d < 8; d++) {
            // broadcast full h vector across the 8-lane group
            float hv[8];
#pragma unroll
            for (int k = 0; k < 8; k++) hv[k] = __shfl_sync(0xffffffffu, h, gb + k);

            // two 4-FMA chains + combine (latency ~20 vs 32 serial)
            float ra = br[d], za = bz[d], qa = bq;
            float rb = wr[4] * hv[4], zb = wz[4] * hv[4], qb = wn[4] * hv[4];
#pragma unroll
            for (int k = 0; k < 4; k++) {
                ra = fmaf(wr[k], hv[k], ra);
                za = fmaf(wz[k], hv[k], za);
                qa = fmaf(wn[k], hv[k], qa);
            }
#pragma unroll
            for (int k = 5; k < 8; k++) {
                rb = fmaf(wr[k], hv[k], rb);
                zb = fmaf(wz[k], hv[k], zb);
                qb = fmaf(wn[k], hv[k], qb);
            }
            float dr = ra + rb, dz = za + zb, q = qa + qb;
            float gn = bn[d];

            // prefetch step t+8+d (off the critical path)
            int s2 = t + 8 + d; if (s2 > SEQ - 1) s2 = SEQ - 1;
            const float* np = gp + (size_t)s2 * 24;
            br[d] = np[j]; bz[d] = np[8 + j]; bn[d] = np[16 + j];

            // r = sigmoid(pre_r): dr is already -log2e*pre_r
            float r  = rcpa(1.f + ex2a(dr));
            float z  = rcpa(1.f + ex2a(dz));
            // off-critical-path helpers for the blend
            float u    = 1.f - z;
            float upzh = fmaf(z, h, u);    // u + z*h
            float m2u  = -2.f * u;
            // n = tanh(v): 2*log2e*v = gn + r*q ; n = 1 - 2/(1+2^na)
            float na = fmaf(r, q, gn);
            float tn = rcpa(1.f + ex2a(na));
            // h' = (1-z)*n + z*h = u*(1-2*tn) + z*h = m2u*tn + (u+zh)
            h = fmaf(m2u, tn, upzh);
        }
    }
    out[chain * 8 + j] = h;
}

extern "C" void kernel_launch(void* const* d_in, const int* in_sizes, int n_in,
                              void* d_out, int out_size) {
    const float* A   = (const float*)d_in[0];
    const float* Win = (const float*)d_in[1];
    const float* bin = (const float*)d_in[2];
    const float* Wih = (const float*)d_in[3];
    const float* Whh = (const float*)d_in[4];
    const float* bih = (const float*)d_in[5];
    const float* bhh = (const float*)d_in[6];

    prep_kernel<<<1, 256>>>(Win, bin, Wih, Whh, bih, bhh);
    proj_kernel<<<NITEMS / 256, 256>>>(A);
    scan_kernel<<<BATCH / 4, 32>>>((float*)d_out);
}

// round 3
// speedup vs baseline: 1.7773x; 1.5612x over previous
#include <cuda_runtime.h>
#include <cstdint>

// TemporalEncoder: fc_in(64->128) + GRU(128->8) over (B=512, S=2048).
//  prep:  W_comb = W_ih @ W_in (24x64). r,z rows scaled 0.5 (sigmoid via HW tanh:
//         sig(x)=0.5+0.5*tanh(x/2)); n rows scaled C2=2*log2(e) (tanh via exp2).
//  proj:  gates = W_comb @ a, smem-staged A, written TRANSPOSED [chain][gate][SEQ].
//  scan:  512 chains x 2048 steps; 8 lanes/chain; float4 gate loads (6 per 8 steps),
//         prefetch one group ahead; tanh.approx for r,z; ex2/rcp for n.

#define BATCH 512
#define SEQ   2048
#define INSZ  64
#define HID   128
#define NITEMS (BATCH * SEQ)

#define C2f (2.8853900817779268f)     // 2*log2(e)
#define H5C2 (1.4426950408889634f)    // 0.5*C2

typedef unsigned long long ull;

__device__ float g_Wc[24 * 64];       // scaled combined weights
__device__ float g_bc[24];            // scaled combined biases
__device__ float g_Whh_s[24 * 8];     // scaled hidden->hidden weights
__device__ float g_bhn_s[8];          // 0.5*C2*bhn
__device__ float g_gbuf[(size_t)BATCH * 24 * SEQ];  // 96 MB, [chain][gate][seq]

__device__ __forceinline__ ull pack2(float lo, float hi) {
    ull r; asm("mov.b64 %0, {%1,%2};" : "=l"(r) : "f"(lo), "f"(hi)); return r;
}
__device__ __forceinline__ ull fma2(ull a, ull b, ull c) {
    ull d; asm("fma.rn.f32x2 %0, %1, %2, %3;" : "=l"(d) : "l"(a), "l"(b), "l"(c)); return d;
}
__device__ __forceinline__ float2 unpack2(ull v) {
    float lo, hi; asm("mov.b64 {%0,%1}, %2;" : "=f"(lo), "=f"(hi) : "l"(v));
    return make_float2(lo, hi);
}
__device__ __forceinline__ float ex2a(float x) {
    float y; asm("ex2.approx.ftz.f32 %0, %1;" : "=f"(y) : "f"(x)); return y;
}
__device__ __forceinline__ float rcpa(float x) {
    float y; asm("rcp.approx.ftz.f32 %0, %1;" : "=f"(y) : "f"(x)); return y;
}
__device__ __forceinline__ float tanha(float x) {
    float y; asm("tanh.approx.f32 %0, %1;" : "=f"(y) : "f"(x)); return y;
}

// ---------------- prep: 6 blocks x 256 threads ----------------
__global__ void __launch_bounds__(256) prep_kernel(
    const float* __restrict__ Win,  // [128,64]
    const float* __restrict__ bin,  // [128]
    const float* __restrict__ Wih,  // [24,128]
    const float* __restrict__ Whh,  // [24,8]
    const float* __restrict__ bih,  // [24]
    const float* __restrict__ bhh)  // [24]
{
    __shared__ float sWin[HID * INSZ];
    __shared__ float sWih[24 * HID];
    __shared__ float sbin[HID];
    int t = threadIdx.x;
    for (int i = t; i < HID * INSZ; i += 256) sWin[i] = Win[i];
    for (int i = t; i < 24 * HID; i += 256) sWih[i] = Wih[i];
    if (t < HID) sbin[t] = bin[t];
    __syncthreads();

    int e = blockIdx.x * 256 + t;     // 0..1535
    int g = e >> 6, i = e & 63;
    float s0 = 0.f, s1 = 0.f, s2 = 0.f, s3 = 0.f;
    for (int h = 0; h < HID; h += 4) {
        s0 = fmaf(sWih[g * HID + h],     sWin[h * INSZ + i],       s0);
        s1 = fmaf(sWih[g * HID + h + 1], sWin[(h + 1) * INSZ + i], s1);
        s2 = fmaf(sWih[g * HID + h + 2], sWin[(h + 2) * INSZ + i], s2);
        s3 = fmaf(sWih[g * HID + h + 3], sWin[(h + 3) * INSZ + i], s3);
    }
    g_Wc[e] = ((g < 16) ? 0.5f : C2f) * ((s0 + s1) + (s2 + s3));

    if (blockIdx.x == 0) {
        if (t < 24) {
            int gg = t;
            float s = 0.f;
            for (int h = 0; h < HID; h++) s = fmaf(sWih[gg * HID + h], sbin[h], s);
            s += bih[gg];
            if (gg < 16) { s += bhh[gg]; g_bc[gg] = 0.5f * s; }   // fold bhr/bhz
            else         {               g_bc[gg] = C2f * s;  }   // bhn goes to bq
        }
        if (t < 24 * 8) {
            int gg = t >> 3;
            g_Whh_s[t] = ((gg < 16) ? 0.5f : H5C2) * Whh[t];
        }
        if (t < 8) g_bhn_s[t] = H5C2 * bhh[16 + t];
    }
}

// ---------------- proj: 128 threads, warp-cooperative A staging ----------------
#define ROWP 68   // padded row stride (floats), 16B aligned
__global__ void __launch_bounds__(128) proj_kernel(const float* __restrict__ A) {
    __shared__ __align__(16) float sW[24 * 64];
    __shared__ float sb[24];
    __shared__ __align__(16) float sA[4 * 32 * ROWP];  // 34.8 KB

    for (int i = threadIdx.x; i < 24 * 64; i += 128) sW[i] = g_Wc[i];
    if (threadIdx.x < 24) sb[threadIdx.x] = g_bc[threadIdx.x];

    int w = threadIdx.x >> 5, lane = threadIdx.x & 31;
    int itemBase = blockIdx.x * 128 + w * 32;     // this warp's 32 items
    float* sAw = sA + w * 32 * ROWP;

    // coalesced load of 32 items x 64 floats (512 float4) into padded smem rows
    const float4* ap = reinterpret_cast<const float4*>(A + (size_t)itemBase * INSZ);
#pragma unroll
    for (int rep = 0; rep < 16; rep++) {
        int f = rep * 32 + lane;            // 0..511
        float4 v = ap[f];
        int it = f >> 4, c = f & 15;
        *reinterpret_cast<float4*>(sAw + it * ROWP + c * 4) = v;
    }
    __syncthreads();

    // pack this lane's item from smem
    ull a2[32];
    const float4* rp = reinterpret_cast<const float4*>(sAw + lane * ROWP);
#pragma unroll
    for (int c = 0; c < 16; c++) {
        float4 v = rp[c];
        a2[2 * c]     = pack2(v.x, v.y);
        a2[2 * c + 1] = pack2(v.z, v.w);
    }

    float res[24];
#pragma unroll
    for (int g = 0; g < 24; g++) {
        const ulonglong2* wp = reinterpret_cast<const ulonglong2*>(sW + g * 64);
        ull acc0 = pack2(sb[g], 0.f);
        ull acc1 = pack2(0.f, 0.f);
#pragma unroll
        for (int p = 0; p < 16; p++) {
            ulonglong2 wv = wp[p];
            acc0 = fma2(wv.x, a2[2 * p], acc0);
            acc1 = fma2(wv.y, a2[2 * p + 1], acc1);
        }
        float2 s0 = unpack2(acc0), s1 = unpack2(acc1);
        res[g] = (s0.x + s0.y) + (s1.x + s1.y);
    }

    // transposed store: [chain][gate][seq]; consecutive lanes -> consecutive s
    int item = itemBase + lane;
    int chain = item >> 11, s = item & 2047;
    float* ob = g_gbuf + (size_t)chain * 24 * SEQ + s;
#pragma unroll
    for (int g = 0; g < 24; g++) ob[g * SEQ] = res[g];
}

// ---------------- scan: sequential GRU, 8 lanes per chain ----------------
__global__ void __launch_bounds__(32) scan_kernel(float* __restrict__ out) {
    int lane  = threadIdx.x;
    int j     = lane & 7;
    int gb    = lane & ~7;
    int chain = blockIdx.x * 4 + (lane >> 3);

    float wr[8], wz[8], wn[8];
#pragma unroll
    for (int k = 0; k < 8; k++) {
        wr[k] = g_Whh_s[j * 8 + k];
        wz[k] = g_Whh_s[(8 + j) * 8 + k];
        wn[k] = g_Whh_s[(16 + j) * 8 + k];
    }
    float bq = g_bhn_s[j];

    const float* pr = g_gbuf + (size_t)chain * 24 * SEQ + j * SEQ;
    const float* pz = pr + 8 * SEQ;
    const float* pn = pr + 16 * SEQ;

    // current 8-step gate group (2 float4 per gate)
    float4 r0 = *reinterpret_cast<const float4*>(pr);
    float4 r1 = *reinterpret_cast<const float4*>(pr + 4);
    float4 z0 = *reinterpret_cast<const float4*>(pz);
    float4 z1 = *reinterpret_cast<const float4*>(pz + 4);
    float4 n0 = *reinterpret_cast<const float4*>(pn);
    float4 n1 = *reinterpret_cast<const float4*>(pn + 4);

    float h = 0.f;

#define STEP(BR, BZ, BN)                                                      \
    {                                                                         \
        float hv[8];                                                          \
        _Pragma("unroll")                                                     \
        for (int k = 0; k < 8; k++) hv[k] = __shfl_sync(0xffffffffu, h, gb + k); \
        float A0 = fmaf(0.5f, h, 0.5f);    /* 0.5*(1+h) */                    \
        float A1 = fmaf(0.5f, h, -0.5f);   /* 0.5*(h-1) */                    \
        float ra = (BR), za = (BZ), qa = bq;                                  \
        float rb = wr[4] * hv[4], zb = wz[4] * hv[4], qb = wn[4] * hv[4];     \
        _Pragma("unroll")                                                     \
        for (int k = 0; k < 4; k++) {                                         \
            ra = fmaf(wr[k], hv[k], ra);                                      \
            za = fmaf(wz[k], hv[k], za);                                      \
            qa = fmaf(wn[k], hv[k], qa);                                      \
        }                                                                     \
        _Pragma("unroll")                                                     \
        for (int k = 5; k < 8; k++) {                                         \
            rb = fmaf(wr[k], hv[k], rb);                                      \
            zb = fmaf(wz[k], hv[k], zb);                                      \
            qb = fmaf(wn[k], hv[k], qb);                                      \
        }                                                                     \
        float tr = tanha(ra + rb);                                            \
        float tz = tanha(za + zb);                                            \
        float qp = qa + qb;                                                   \
        float na = fmaf(qp, tr, (BN) + qp);                                   \
        float tn = rcpa(1.f + ex2a(na));   /* n = 1 - 2*tn */                 \
        h = fmaf(tz, A1 + tn, A0 - tn);                                       \
    }

#define GROUP8                                                                \
    STEP(r0.x, z0.x, n0.x) STEP(r0.y, z0.y, n0.y)                             \
    STEP(r0.z, z0.z, n0.z) STEP(r0.w, z0.w, n0.w)                             \
    STEP(r1.x, z1.x, n1.x) STEP(r1.y, z1.y, n1.y)                             \
    STEP(r1.z, z1.z, n1.z) STEP(r1.w, z1.w, n1.w)

    for (int t = 0; t < SEQ - 8; t += 8) {
        // prefetch next group (constant-offset addressing, off critical path)
        float4 R0 = *reinterpret_cast<const float4*>(pr + t + 8);
        float4 R1 = *reinterpret_cast<const float4*>(pr + t + 12);
        float4 Z0 = *reinterpret_cast<const float4*>(pz + t + 8);
        float4 Z1 = *reinterpret_cast<const float4*>(pz + t + 12);
        float4 N0 = *reinterpret_cast<const float4*>(pn + t + 8);
        float4 N1 = *reinterpret_cast<const float4*>(pn + t + 12);
        GROUP8
        r0 = R0; r1 = R1; z0 = Z0; z1 = Z1; n0 = N0; n1 = N1;
    }
    GROUP8   // final 8 steps

    out[chain * 8 + j] = h;
}

extern "C" void kernel_launch(void* const* d_in, const int* in_sizes, int n_in,
                              void* d_out, int out_size) {
    const float* A   = (const float*)d_in[0];
    const float* Win = (const float*)d_in[1];
    const float* bin = (const float*)d_in[2];
    const float* Wih = (const float*)d_in[3];
    const float* Whh = (const float*)d_in[4];
    const float* bih = (const float*)d_in[5];
    const float* bhh = (const float*)d_in[6];

    prep_kernel<<<6, 256>>>(Win, bin, Wih, Whh, bih, bhh);
    proj_kernel<<<NITEMS / 128, 128>>>(A);
    scan_kernel<<<BATCH / 4, 32>>>((float*)d_out);
}

// round 4
// speedup vs baseline: 2.5038x; 1.4087x over previous
#include <cuda_runtime.h>
#include <cstdint>

// TemporalEncoder: fc_in(64->128) + GRU(128->8) over (B=512, S=2048).
// Fused producer/consumer kernel:
//   128 blocks x 256 threads; block b owns chains 4b..4b+3.
//   warps 0-6: projection gates = W_comb @ a for this block's chains,
//              64-step windows, double-buffered in smem.
//   warp 7:    4-chain GRU scan consuming gate windows from smem.
// prep kernel folds W_ih@W_in, biases, and the sigmoid-as-tanh 0.5 scalings.

#define BATCH 512
#define SEQ   2048
#define INSZ  64
#define HID   128
#define WSTEP 64                 // window steps
#define NWIN  (SEQ / WSTEP)      // 32
#define GROW  97                 // gate row stride (floats), bank-engineered
#define STG   (WSTEP * GROW)     // 6208 floats per stage
#define ROWP  68                 // padded A row stride (floats)

typedef unsigned long long ull;

__device__ float g_Wc[24 * 64];   // combined weights (r,z rows *0.5; n rows *1)
__device__ float g_bc[24];        // combined biases  (r,z incl bhh, *0.5; n *1)
__device__ float g_Whh_s[24 * 8]; // hidden weights   (r,z *0.5; n *0.5 for q')
__device__ float g_bhn_s[8];      // 0.5*bhn

__device__ __forceinline__ ull pack2(float lo, float hi) {
    ull r; asm("mov.b64 %0, {%1,%2};" : "=l"(r) : "f"(lo), "f"(hi)); return r;
}
__device__ __forceinline__ ull fma2(ull a, ull b, ull c) {
    ull d; asm("fma.rn.f32x2 %0, %1, %2, %3;" : "=l"(d) : "l"(a), "l"(b), "l"(c)); return d;
}
__device__ __forceinline__ float2 unpack2(ull v) {
    float lo, hi; asm("mov.b64 {%0,%1}, %2;" : "=f"(lo), "=f"(hi) : "l"(v));
    return make_float2(lo, hi);
}
__device__ __forceinline__ float tanha(float x) {
    float y; asm("tanh.approx.f32 %0, %1;" : "=f"(y) : "f"(x)); return y;
}

// ---------------- prep ----------------
__global__ void __launch_bounds__(256) prep_kernel(
    const float* __restrict__ Win,  // [128,64]
    const float* __restrict__ bin,  // [128]
    const float* __restrict__ Wih,  // [24,128]
    const float* __restrict__ Whh,  // [24,8]
    const float* __restrict__ bih,  // [24]
    const float* __restrict__ bhh)  // [24]
{
    __shared__ float sWin[HID * INSZ];
    __shared__ float sWih[24 * HID];
    __shared__ float sbin[HID];
    int t = threadIdx.x;
    for (int i = t; i < HID * INSZ; i += 256) sWin[i] = Win[i];
    for (int i = t; i < 24 * HID; i += 256) sWih[i] = Wih[i];
    if (t < HID) sbin[t] = bin[t];
    __syncthreads();

    int e = blockIdx.x * 256 + t;     // 0..1535
    int g = e >> 6, i = e & 63;
    float s0 = 0.f, s1 = 0.f, s2 = 0.f, s3 = 0.f;
    for (int h = 0; h < HID; h += 4) {
        s0 = fmaf(sWih[g * HID + h],     sWin[h * INSZ + i],       s0);
        s1 = fmaf(sWih[g * HID + h + 1], sWin[(h + 1) * INSZ + i], s1);
        s2 = fmaf(sWih[g * HID + h + 2], sWin[(h + 2) * INSZ + i], s2);
        s3 = fmaf(sWih[g * HID + h + 3], sWin[(h + 3) * INSZ + i], s3);
    }
    g_Wc[e] = ((g < 16) ? 0.5f : 1.0f) * ((s0 + s1) + (s2 + s3));

    if (blockIdx.x == 0) {
        if (t < 24) {
            int gg = t;
            float s = 0.f;
            for (int h = 0; h < HID; h++) s = fmaf(sWih[gg * HID + h], sbin[h], s);
            s += bih[gg];
            if (gg < 16) { s += bhh[gg]; g_bc[gg] = 0.5f * s; }  // fold bhr/bhz
            else         {               g_bc[gg] = s;        }  // xn bias raw
        }
        if (t < 24 * 8) g_Whh_s[t] = 0.5f * Whh[t];              // all rows *0.5
        if (t < 8) g_bhn_s[t] = 0.5f * bhh[16 + t];
    }
}

// ---------------- fused proj + scan ----------------
__global__ void __launch_bounds__(256) fused_kernel(const float* __restrict__ A,
                                                    float* __restrict__ out) {
    extern __shared__ float sm[];
    float* sW = sm;                       // 1536
    float* sb = sW + 1536;                // 32
    float* sG = sb + 32;                  // 2 * STG = 12416
    float* sA = sG + 2 * STG;             // 7 * 32 * ROWP = 15232

    int tid = threadIdx.x;
    int wid = tid >> 5, lane = tid & 31;
    int chainBase = blockIdx.x * 4;

    for (int i = tid; i < 24 * 64; i += 256) sW[i] = g_Wc[i];
    if (tid < 24) sb[tid] = g_bc[tid];

    // ---- consumer (warp 7) setup ----
    float wr[8], wz[8], wn[8], bq = 0.f, h = 0.f;
    int j = lane & 7, c = lane >> 3, gb2 = lane & ~7;
    if (wid == 7) {
#pragma unroll
        for (int k = 0; k < 8; k++) {
            wr[k] = g_Whh_s[j * 8 + k];
            wz[k] = g_Whh_s[(8 + j) * 8 + k];
            wn[k] = g_Whh_s[(16 + j) * 8 + k];
        }
        bq = g_bhn_s[j];
    }
    float* sAw = sA + wid * 32 * ROWP;
    __syncthreads();

    // ---- producer: fill one window into a stage ----
    auto fill = [&](int w, int stage) {
        float* gst = sG + stage * STG;
        for (int b = wid; b < 8; b += 7) {          // warp p: batch p; warp0 also batch 7
            int cb = b >> 1;
            int sHalf = (b & 1) * 32;               // step offset within window
            const float4* ap = reinterpret_cast<const float4*>(
                A + ((size_t)(chainBase + cb) * SEQ + w * WSTEP + sHalf) * INSZ);
            __syncwarp();
            // stage 32 items x 64 floats (8KB) coalesced into padded smem
#pragma unroll
            for (int rep = 0; rep < 16; rep++) {
                int f = rep * 32 + lane;
                float4 v = ap[f];
                int it = f >> 4, cc = f & 15;
                *reinterpret_cast<float4*>(sAw + it * ROWP + cc * 4) = v;
            }
            __syncwarp();
            // pack this lane's item (step sHalf+lane of chain cb)
            ull a2[32];
            const float4* rp = reinterpret_cast<const float4*>(sAw + lane * ROWP);
#pragma unroll
            for (int cc = 0; cc < 16; cc++) {
                float4 v = rp[cc];
                a2[2 * cc]     = pack2(v.x, v.y);
                a2[2 * cc + 1] = pack2(v.z, v.w);
            }
            int stepW = sHalf + lane;
            float* gout = gst + stepW * GROW + cb;
#pragma unroll
            for (int g = 0; g < 24; g++) {
                const ulonglong2* wp = reinterpret_cast<const ulonglong2*>(sW + g * 64);
                ull acc0 = pack2(sb[g], 0.f);
                ull acc1 = pack2(0.f, 0.f);
#pragma unroll
                for (int p = 0; p < 16; p++) {
                    ulonglong2 wv = wp[p];
                    acc0 = fma2(wv.x, a2[2 * p], acc0);
                    acc1 = fma2(wv.y, a2[2 * p + 1], acc1);
                }
                float2 q0 = unpack2(acc0), q1 = unpack2(acc1);
                gout[g * 4] = (q0.x + q0.y) + (q1.x + q1.y);
            }
        }
    };

    // prologue: window 0 into stage 0
    if (wid < 7) fill(0, 0);
    __syncthreads();

    for (int w = 0; w < NWIN; w++) {
        int stage = w & 1;
        if (wid < 7) {
            if (w + 1 < NWIN) fill(w + 1, stage ^ 1);
        } else {
            // ---- consumer: 64 GRU steps from this stage ----
            const float* gbase = sG + stage * STG;
            int o = 4 * j + c;
            float xr = gbase[o], xz = gbase[o + 32], xn = gbase[o + 64];
#pragma unroll 8
            for (int t = 0; t < WSTEP; t++) {
                int t2 = (t + 1 < WSTEP) ? t + 1 : t;
                const float* np = gbase + t2 * GROW + o;
                float nxr = np[0], nxz = np[32], nxn = np[64];

                float hv[8];
#pragma unroll
                for (int k = 0; k < 8; k++) hv[k] = __shfl_sync(0xffffffffu, h, gb2 + k);

                float ra = xr, za = xz, qa = bq;
                float rb = wr[4] * hv[4], zb = wz[4] * hv[4], qb = wn[4] * hv[4];
#pragma unroll
                for (int k = 0; k < 4; k++) {
                    ra = fmaf(wr[k], hv[k], ra);
                    za = fmaf(wz[k], hv[k], za);
                    qa = fmaf(wn[k], hv[k], qa);
                }
#pragma unroll
                for (int k = 5; k < 8; k++) {
                    rb = fmaf(wr[k], hv[k], rb);
                    zb = fmaf(wz[k], hv[k], zb);
                    qb = fmaf(wn[k], hv[k], qb);
                }
                float tr = tanha(ra + rb);
                float tz = tanha(za + zb);
                float qp = qa + qb;                 // q' = 0.5*(Whn h + bhn)
                // off-critical-path blend coefficients
                float u0 = 0.5f * fmaf(tz, h, h);   // 0.5*(1+tz)*h = z*h
                float cc = fmaf(-0.5f, tz, 0.5f);   // 0.5*(1-tz) = 1-z
                // n = tanh(xn + r*q), r = 0.5 + 0.5*tr
                float narg = fmaf(tr, qp, xn + qp);
                float n = tanha(narg);
                h = fmaf(cc, n, u0);

                xr = nxr; xz = nxz; xn = nxn;
            }
        }
        __syncthreads();
    }

    if (wid == 7) out[(chainBase + c) * 8 + j] = h;
}

extern "C" void kernel_launch(void* const* d_in, const int* in_sizes, int n_in,
                              void* d_out, int out_size) {
    const float* A   = (const float*)d_in[0];
    const float* Win = (const float*)d_in[1];
    const float* bin = (const float*)d_in[2];
    const float* Wih = (const float*)d_in[3];
    const float* Whh = (const float*)d_in[4];
    const float* bih = (const float*)d_in[5];
    const float* bhh = (const float*)d_in[6];

    static int configured = 0;
    size_t smem = (1536 + 32 + 2 * STG + 7 * 32 * ROWP) * sizeof(float);  // ~117 KB
    if (!configured) {
        cudaFuncSetAttribute(fused_kernel, cudaFuncAttributeMaxDynamicSharedMemorySize,
                             (int)smem);
        configured = 1;
    }

    prep_kernel<<<6, 256>>>(Win, bin, Wih, Whh, bih, bhh);
    fused_kernel<<<BATCH / 4, 256, smem>>>(A, (float*)d_out);
}